// round 1
// baseline (speedup 1.0000x reference)
#include <cuda_runtime.h>
#include <cstdint>

// PolarToCartesianGrid: batched scatter-add of polar-cell intensities into a
// cartesian voxel grid. indices are fixed int32 (precomputed host-side by the
// reference), all in-bounds by construction of the radar geometry.
//
// Strategy:
//   1) cudaMemsetAsync the 524MB output to zero (HBM-write floor).
//   2) One thread per polar cell; loop over the 16 batches.
//      Warp-aggregated atomics: lanes sharing a voxel index (common at small
//      range, where whole az/el arcs collapse into one voxel) combine their
//      values with a shuffle reduction tree; only the group leader issues the
//      atomicAdd. Group structure is batch-invariant -> computed once.

__global__ void polar_scatter_kernel(const float* __restrict__ polar,
                                     const int*   __restrict__ vidx,
                                     float*       __restrict__ out,
                                     int n_cells, int batches, long long n_vox)
{
    const int cell = blockIdx.x * blockDim.x + threadIdx.x;
    if (cell >= n_cells) return;                 // n_cells % 256 == 0 -> no divergence
    const unsigned FULL = 0xFFFFFFFFu;
    const int lane = threadIdx.x & 31;

    const int idx = vidx[cell];

    // --- batch-invariant group structure -----------------------------------
    // peers: lanes in this warp whose voxel index equals mine
    const unsigned peers = __match_any_sync(FULL, idx);
    const int rank = __popc(peers & ((1u << lane) - 1u));   // my rank in group

    // source lane for reduction step d = lane of peer at rank+d
    // __fns(mask, base, n): position of n-th set bit counting from 'base'
    // (base's own bit counts as n=1). Returns 0xFFFFFFFF if absent.
    const unsigned s1  = __fns(peers, lane, 2);
    const unsigned s2  = __fns(peers, lane, 3);
    const unsigned s4  = __fns(peers, lane, 5);
    const unsigned s8  = __fns(peers, lane, 9);
    const unsigned s16 = __fns(peers, lane, 17);
    const bool v1  = (s1  < 32);
    const bool v2  = (s2  < 32);
    const bool v4  = (s4  < 32);
    const bool v8  = (s8  < 32);
    const bool v16 = (s16 < 32);

    // --- per-batch: load, group-reduce, single atomic per group ------------
    #pragma unroll
    for (int b = 0; b < 16; ++b) {
        if (b >= batches) break;
        float v = __ldg(polar + (size_t)b * n_cells + cell);
        float t;
        // rank-doubling segmented reduction: after step d, v = sum of group
        // ranks [rank, rank+2d). shfl reads pre-update values, so the tree is
        // exact. Lanes outside the group never contribute (v* false).
        t = __shfl_sync(FULL, v, s1  & 31); if (v1)  v += t;
        t = __shfl_sync(FULL, v, s2  & 31); if (v2)  v += t;
        t = __shfl_sync(FULL, v, s4  & 31); if (v4)  v += t;
        t = __shfl_sync(FULL, v, s8  & 31); if (v8)  v += t;
        t = __shfl_sync(FULL, v, s16 & 31); if (v16) v += t;
        if (rank == 0) {
            atomicAdd(out + (long long)b * n_vox + idx, v);
        }
    }
}

extern "C" void kernel_launch(void* const* d_in, const int* in_sizes, int n_in,
                              void* d_out, int out_size)
{
    const float* polar = (const float*)d_in[0];          // [B,1,El,R,Az] f32
    const int*   vidx  = (const int*)d_in[1];            // [El*R*Az] int32
    float*       out   = (float*)d_out;                  // [B,1,Z,Y,X] f32

    const int n_cells = in_sizes[1];                     // El*R*Az = 1,048,576
    const int batches = in_sizes[0] / n_cells;           // 16
    const long long n_vox = (long long)out_size / batches; // 8,192,000

    // zero the whole output (poisoned before timing); graph-capturable node
    cudaMemsetAsync(d_out, 0, (size_t)out_size * sizeof(float), 0);

    const int threads = 256;
    const int blocks  = (n_cells + threads - 1) / threads;
    polar_scatter_kernel<<<blocks, threads>>>(polar, vidx, out,
                                              n_cells, batches, n_vox);
}